// round 7
// baseline (speedup 1.0000x reference)
#include <cuda_runtime.h>
#include <cuda_bf16.h>
#include <cstdint>

#define N_NODES 100000
#define N_EDGES 2000000
#define DIM 64
#define CAP 96   // max in-degree capacity (deg ~ Poisson(20); P(max>96) ~ 0)

typedef unsigned long long ull;

// Scratch (no cudaMalloc allowed)
__device__ int g_cnt[N_NODES];
__device__ __align__(16) int g_adj[(size_t)N_NODES * CAP];          // 38.4 MB
__device__ __align__(16) float g_agg[(size_t)N_NODES * DIM];        // mean (pre-scaled)
__device__ __align__(16) float g_h1[(size_t)N_NODES * DIM];

// ---- f32x2 packed-FMA helpers (sm_103a) -----------------------------------
__device__ __forceinline__ ull rep2(float x) {
    ull r; asm("mov.b64 %0, {%1, %1};" : "=l"(r) : "f"(x)); return r;
}
__device__ __forceinline__ void fma2(ull& d, ull a, ull b) {
    asm("fma.rn.f32x2 %0, %1, %2, %0;" : "+l"(d) : "l"(a), "l"(b));
}
__device__ __forceinline__ float2 unpack2(ull v) {
    float2 f; asm("mov.b64 {%0, %1}, %2;" : "=f"(f.x), "=f"(f.y) : "l"(v)); return f;
}

// ---------------------------------------------------------------------------
// Build per-destination adjacency buckets: g_adj[dst*CAP + slot] = src.
// 4 edges per thread, vectorized edge loads. Reused by both layers.
// ---------------------------------------------------------------------------
__global__ void __launch_bounds__(256)
build_adj_kernel(const int* __restrict__ ei)
{
    unsigned e0 = (blockIdx.x * blockDim.x + threadIdx.x) * 4;
    if (e0 >= N_EDGES) return;
    int4 s4 = *reinterpret_cast<const int4*>(ei + e0);
    int4 d4 = *reinterpret_cast<const int4*>(ei + N_EDGES + e0);
    int ss[4] = {s4.x, s4.y, s4.z, s4.w};
    int dd[4] = {d4.x, d4.y, d4.z, d4.w};
    #pragma unroll
    for (int i = 0; i < 4; i++) {
        int slot = atomicAdd(&g_cnt[dd[i]], 1);
        if (slot < CAP) g_adj[(size_t)dd[i] * CAP + slot] = ss[i];
    }
}

// ---------------------------------------------------------------------------
// Gather + mean: g_agg[node] = (1/max(deg,1)) * sum_{src in adj[node]} h[src]
// Warp per node; HALF-warp per neighbor row (16 lanes x float4 = 256B row).
// Indices fetched as warp-uniform int4. Unroll 8 for MLP. (Near LTS cap.)
// ---------------------------------------------------------------------------
__global__ void __launch_bounds__(256)
gather_kernel(const float* __restrict__ h)
{
    const int lane = threadIdx.x & 31;
    const int half = lane >> 4;          // 0: even neighbor, 1: odd neighbor
    const int sub  = lane & 15;          // float4 chunk within row
    const int warp = threadIdx.x >> 5;
    const int node = blockIdx.x * 8 + warp;   // grid exact (100000/8)

    const int deg = g_cnt[node];
    const int cnt = min(deg, CAP);
    const int* __restrict__ adj = g_adj + node * CAP;
    const float4* __restrict__ h4 = reinterpret_cast<const float4*>(h);

    float4 acc = make_float4(0.f, 0.f, 0.f, 0.f);
    int j = 0;
    for (; j + 8 <= cnt; j += 8) {
        int4 ia = *reinterpret_cast<const int4*>(adj + j);
        int4 ib = *reinterpret_cast<const int4*>(adj + j + 4);
        int s0 = half ? ia.y : ia.x;
        int s1 = half ? ia.w : ia.z;
        int s2 = half ? ib.y : ib.x;
        int s3 = half ? ib.w : ib.z;
        float4 v0 = h4[s0 * 16 + sub];
        float4 v1 = h4[s1 * 16 + sub];
        float4 v2 = h4[s2 * 16 + sub];
        float4 v3 = h4[s3 * 16 + sub];
        acc.x += (v0.x + v1.x) + (v2.x + v3.x);
        acc.y += (v0.y + v1.y) + (v2.y + v3.y);
        acc.z += (v0.z + v1.z) + (v2.z + v3.z);
        acc.w += (v0.w + v1.w) + (v2.w + v3.w);
    }
    for (; j + 2 <= cnt; j += 2) {
        int2 ia = *reinterpret_cast<const int2*>(adj + j);
        int s = half ? ia.y : ia.x;
        float4 v = h4[s * 16 + sub];
        acc.x += v.x; acc.y += v.y; acc.z += v.z; acc.w += v.w;
    }
    if (j < cnt && half == 0) {          // odd trailing neighbor
        float4 v = h4[adj[j] * 16 + sub];
        acc.x += v.x; acc.y += v.y; acc.z += v.z; acc.w += v.w;
    }

    // Combine the two half-warps
    acc.x += __shfl_xor_sync(0xffffffffu, acc.x, 16);
    acc.y += __shfl_xor_sync(0xffffffffu, acc.y, 16);
    acc.z += __shfl_xor_sync(0xffffffffu, acc.z, 16);
    acc.w += __shfl_xor_sync(0xffffffffu, acc.w, 16);

    if (half == 0) {
        float inv = 1.0f / fmaxf((float)deg, 1.0f);
        acc.x *= inv; acc.y *= inv; acc.z *= inv; acc.w *= inv;
        reinterpret_cast<float4*>(g_agg)[node * 16 + sub] = acc;
    }
}

// ---------------------------------------------------------------------------
// Transform: out = act( concat(h, agg) @ W + b ), register-tiled SGEMM with
// packed fma.rn.f32x2. Block: 128 nodes x 64 cols, K=128 in smem.
// Thread: 8 nodes x 8 cols = 32 FFMA2/k. Node-pair operands come straight
// out of LDS.128 as ulonglong2 (no pack movs); only the broadcast b operand
// needs a {b,b} replication mov (ALU pipe, hidden under FMA).
// ---------------------------------------------------------------------------
template <bool RELU>
__global__ void __launch_bounds__(128)
transform_kernel(const float* __restrict__ h,
                 const float* __restrict__ W,
                 const float* __restrict__ b,
                 float* __restrict__ out)
{
    extern __shared__ float smem[];
    float* As = smem;                 // [128 k][128 node]  64KB
    float* Bs = smem + 128 * 128;     // [128 k][64 col]    32KB
    __shared__ float bs[64];

    const int tid = threadIdx.x;

    // Stage W and bias
    {
        const float4* W4 = reinterpret_cast<const float4*>(W);
        float4* Bs4 = reinterpret_cast<float4*>(Bs);
        #pragma unroll
        for (int i = 0; i < 16; i++) Bs4[i * 128 + tid] = W4[i * 128 + tid];
        if (tid < 64) bs[tid] = b[tid];
    }

    // Stage A tile transposed: As[k][node_l]; k 0..63 from h, 64..127 from agg.
    const int base_node = blockIdx.x * 128;
    const float4* __restrict__ h4 = reinterpret_cast<const float4*>(h);
    const float4* __restrict__ a4 = reinterpret_cast<const float4*>(g_agg);

    #pragma unroll
    for (int g = 0; g < 4; g++) {
        int node_l = g * 32 + (tid & 31);
        int node = base_node + node_l;
        if (node >= N_NODES) node = N_NODES - 1;   // clamp; stores guarded
        #pragma unroll
        for (int c = tid >> 5; c < 32; c += 4) {
            float4 v;
            int k0;
            if (c < 16) { v = h4[(size_t)node * 16 + c];        k0 = c * 4; }
            else        { v = a4[(size_t)node * 16 + (c - 16)]; k0 = 64 + (c - 16) * 4; }
            As[(k0 + 0) * 128 + node_l] = v.x;
            As[(k0 + 1) * 128 + node_l] = v.y;
            As[(k0 + 2) * 128 + node_l] = v.z;
            As[(k0 + 3) * 128 + node_l] = v.w;
        }
    }
    __syncthreads();

    const int tx = tid & 15;    // node group (8 nodes)
    const int ty = tid >> 4;    // col group (8 cols)

    // As rows viewed as ulonglong2: each element = 2 node-pairs (4 floats).
    const ulonglong2* __restrict__ Asu = reinterpret_cast<const ulonglong2*>(As);
    const float4* __restrict__ Bs4 = reinterpret_cast<const float4*>(Bs);

    // acc2[i2][j]: f32x2 over node pair (2*i2, 2*i2+1), column j
    ull acc2[4][8];
    #pragma unroll
    for (int i = 0; i < 4; i++)
        #pragma unroll
        for (int j = 0; j < 8; j++) acc2[i][j] = 0ull;

    #pragma unroll 8
    for (int k = 0; k < 128; k++) {
        ulonglong2 u0 = Asu[k * 32 + tx * 2];       // nodes 8tx+0..3 (2 pairs)
        ulonglong2 u1 = Asu[k * 32 + tx * 2 + 1];   // nodes 8tx+4..7 (2 pairs)
        float4 b0 = Bs4[k * 16 + ty * 2];
        float4 b1 = Bs4[k * 16 + ty * 2 + 1];
        ull av[4] = {u0.x, u0.y, u1.x, u1.y};
        float bv[8] = {b0.x, b0.y, b0.z, b0.w, b1.x, b1.y, b1.z, b1.w};
        #pragma unroll
        for (int j = 0; j < 8; j++) {
            ull bj = rep2(bv[j]);
            #pragma unroll
            for (int i = 0; i < 4; i++) fma2(acc2[i][j], av[i], bj);
        }
    }

    // Epilogue: unpack node pairs, bias (+ReLU), vectorized stores
    float4* out4 = reinterpret_cast<float4*>(out);
    #pragma unroll
    for (int i2 = 0; i2 < 4; i2++) {
        float oe[8], oo[8];
        #pragma unroll
        for (int j = 0; j < 8; j++) {
            float2 p = unpack2(acc2[i2][j]);
            float bb = bs[ty * 8 + j];
            float e = p.x + bb, o = p.y + bb;
            if (RELU) { e = fmaxf(e, 0.0f); o = fmaxf(o, 0.0f); }
            oe[j] = e; oo[j] = o;
        }
        int node_e = base_node + tx * 8 + 2 * i2;
        if (node_e < N_NODES) {
            out4[(size_t)node_e * 16 + ty * 2]     = make_float4(oe[0], oe[1], oe[2], oe[3]);
            out4[(size_t)node_e * 16 + ty * 2 + 1] = make_float4(oe[4], oe[5], oe[6], oe[7]);
        }
        if (node_e + 1 < N_NODES) {
            out4[(size_t)(node_e + 1) * 16 + ty * 2]     = make_float4(oo[0], oo[1], oo[2], oo[3]);
            out4[(size_t)(node_e + 1) * 16 + ty * 2 + 1] = make_float4(oo[4], oo[5], oo[6], oo[7]);
        }
    }
}

extern "C" void kernel_launch(void* const* d_in, const int* in_sizes, int n_in,
                              void* d_out, int out_size)
{
    const float* x  = (const float*)d_in[0];
    const int*   ei = (const int*)  d_in[1];
    const float* W0 = (const float*)d_in[2];
    const float* b0 = (const float*)d_in[3];
    const float* W1 = (const float*)d_in[4];
    const float* b1 = (const float*)d_in[5];
    float* out = (float*)d_out;

    void *cnt_ptr = nullptr, *h1_ptr = nullptr;
    cudaGetSymbolAddress(&cnt_ptr, g_cnt);
    cudaGetSymbolAddress(&h1_ptr,  g_h1);
    float* h1 = (float*)h1_ptr;

    const int smem_bytes = (128 * 128 + 128 * 64) * sizeof(float);  // 96KB
    cudaFuncSetAttribute(transform_kernel<true>,
                         cudaFuncAttributeMaxDynamicSharedMemorySize, smem_bytes);
    cudaFuncSetAttribute(transform_kernel<false>,
                         cudaFuncAttributeMaxDynamicSharedMemorySize, smem_bytes);

    const int build_blocks  = (N_EDGES / 4 + 255) / 256;
    const int gather_blocks = N_NODES / 8;                 // exact
    const int xform_blocks  = (N_NODES + 127) / 128;

    // Adjacency (shared by both layers)
    cudaMemsetAsync(cnt_ptr, 0, N_NODES * sizeof(int));
    build_adj_kernel<<<build_blocks, 256>>>(ei);

    // ---- Layer 0 ----
    gather_kernel<<<gather_blocks, 256>>>(x);
    transform_kernel<true><<<xform_blocks, 128, smem_bytes>>>(x, W0, b0, h1);

    // ---- Layer 1 ----
    gather_kernel<<<gather_blocks, 256>>>(h1);
    transform_kernel<false><<<xform_blocks, 128, smem_bytes>>>(h1, W1, b1, out);
}